// round 9
// baseline (speedup 1.0000x reference)
#include <cuda_runtime.h>
#include <cuda_bf16.h>
#include <mma.h>
#include <type_traits>

// MonarchAttention on GB300 — WMMA bf16 (HMMA) 3-term-split GEMM engine, v2:
// 256 threads / 8 warps per CTA (4 m-tiles x 2 n-pairs per GEMM) for 2x
// latency hiding vs v1. Same smem footprint -> 4 CTAs/SM.
// B=4,H=16 -> BH=64; N=4096, D=64, b=m=64, STEPS=3.

using namespace nvcuda;
typedef unsigned int u32;

#define SCALE 0.125f
#define LDB 72   // bf16 tile row stride (144B: conflict-free LDSM)
#define LDC 68   // f32 C row stride

// smem layout (bytes)
#define OFF_AH 0
#define OFF_AL 9216
#define OFF_BH 18432
#define OFF_BL 27648
#define OFF_C  36864          // 64*68*4 = 17408
#define OFF_W  54272          // 128 f32 (ent + w)
#define OFF_VH 54784
#define OFF_VL 64000
#define SMEM_SMALL 54784
#define SMEM_BIG   73216

__device__ float g_qmean[262144];     // [bh][s][d]
__device__ float g_ent  [262144];     // [bh][s][j]
__device__ float g_qbar [16777216];   // [bh][j][s][d]
__device__ float g_kbar [16777216];   // [bh][s][j][d]
__device__ float g_vbar [16777216];   // [bh][s][j][d]

// ---------------------------------------------------------------------------
// staging: 64x64 f32 (row stride rs) -> hi/lo bf16 tiles, row-major stride LDB
// 256 threads
// ---------------------------------------------------------------------------
__device__ __forceinline__ u32 pack2(float a, float b) {
    return (u32)__bfloat16_as_ushort(__float2bfloat16(a)) |
           ((u32)__bfloat16_as_ushort(__float2bfloat16(b)) << 16);
}
__device__ __forceinline__ void stageHL(__nv_bfloat16* Th, __nv_bfloat16* Tl,
                                        const float* src, int rs, int tid) {
#pragma unroll
    for (int it = 0; it < 4; ++it) {
        int lin = it * 256 + tid;            // 1024 float4 chunks
        int r = lin >> 4, c4 = (lin & 15) << 2;
        float4 v = *reinterpret_cast<const float4*>(src + r * rs + c4);
        float h0 = __bfloat162float(__float2bfloat16(v.x));
        float h1 = __bfloat162float(__float2bfloat16(v.y));
        float h2 = __bfloat162float(__float2bfloat16(v.z));
        float h3 = __bfloat162float(__float2bfloat16(v.w));
        uint2 H = make_uint2(pack2(v.x, v.y), pack2(v.z, v.w));
        uint2 L = make_uint2(pack2(v.x - h0, v.y - h1), pack2(v.z - h2, v.w - h3));
        *reinterpret_cast<uint2*>(Th + r * LDB + c4) = H;
        *reinterpret_cast<uint2*>(Tl + r * LDB + c4) = L;
    }
}
// stage one register row f[64] -> row r of hi/lo tiles
__device__ __forceinline__ void stageRow(__nv_bfloat16* Th, __nv_bfloat16* Tl,
                                         const float* f, int r) {
#pragma unroll
    for (int c = 0; c < 64; c += 4) {
        float h0 = __bfloat162float(__float2bfloat16(f[c]));
        float h1 = __bfloat162float(__float2bfloat16(f[c + 1]));
        float h2 = __bfloat162float(__float2bfloat16(f[c + 2]));
        float h3 = __bfloat162float(__float2bfloat16(f[c + 3]));
        *reinterpret_cast<uint2*>(Th + r * LDB + c) =
            make_uint2(pack2(f[c], f[c + 1]), pack2(f[c + 2], f[c + 3]));
        *reinterpret_cast<uint2*>(Tl + r * LDB + c) =
            make_uint2(pack2(f[c] - h0, f[c + 1] - h1),
                       pack2(f[c + 2] - h2, f[c + 3] - h3));
    }
}

// ---------------------------------------------------------------------------
// C[64x64 f32, stride LDC] = A x B (3-term bf16 split), 8 warps:
// warp = (m-tile 0..3) x (n-pair 0..1); each warp does 2 n-tiles.
// AROW: A fragment row_major (A stored (m,k)) else col_major (A stored (k,m)).
// BROW: B fragment row_major (B stored (k,n)) else col_major (B stored (n,k)).
// ---------------------------------------------------------------------------
template <bool AROW, bool BROW>
__device__ __forceinline__ void wgemm3(const __nv_bfloat16* Ah, const __nv_bfloat16* Al,
                                       const __nv_bfloat16* Bh, const __nv_bfloat16* Bl,
                                       float* C, int wid) {
    using LA = typename std::conditional<AROW, wmma::row_major, wmma::col_major>::type;
    using LB = typename std::conditional<BROW, wmma::row_major, wmma::col_major>::type;
    wmma::fragment<wmma::matrix_a, 16, 16, 16, __nv_bfloat16, LA> ah[4], al[4];
    int m0 = (wid >> 1) << 4;
    int ntb = (wid & 1) << 1;
#pragma unroll
    for (int kt = 0; kt < 4; ++kt) {
        int aoff = AROW ? m0 * LDB + (kt << 4) : m0 + (kt << 4) * LDB;
        wmma::load_matrix_sync(ah[kt], Ah + aoff, LDB);
        wmma::load_matrix_sync(al[kt], Al + aoff, LDB);
    }
#pragma unroll
    for (int q = 0; q < 2; ++q) {
        int nt = ntb + q;
        wmma::fragment<wmma::accumulator, 16, 16, 16, float> c;
        wmma::fill_fragment(c, 0.0f);
#pragma unroll
        for (int kt = 0; kt < 4; ++kt) {
            int boff = BROW ? (kt << 4) * LDB + (nt << 4) : (kt << 4) + (nt << 4) * LDB;
            wmma::fragment<wmma::matrix_b, 16, 16, 16, __nv_bfloat16, LB> bh, bl;
            wmma::load_matrix_sync(bh, Bh + boff, LDB);
            wmma::load_matrix_sync(bl, Bl + boff, LDB);
            wmma::mma_sync(c, ah[kt], bh, c);
            wmma::mma_sync(c, ah[kt], bl, c);
            wmma::mma_sync(c, al[kt], bh, c);
        }
        wmma::store_matrix_sync(C + m0 * LDC + (nt << 4), c, LDC, wmma::mem_row_major);
    }
}

// ---------------------------------------------------------------------------
// qmean[bh][s][d] = mean_i Q[bh][i][s][d]
// ---------------------------------------------------------------------------
__global__ void qmean_kernel(const float* __restrict__ Q) {
    int bid = blockIdx.x;
    int bh = bid >> 4;
    int s = ((bid & 15) << 2) + (threadIdx.x >> 6);
    int d = threadIdx.x & 63;
    const float* base = Q + bh * 262144 + s * 64 + d;
    float acc = 0.f;
#pragma unroll 16
    for (int i = 0; i < 64; ++i) acc += base[i * 4096];
    g_qmean[(bh << 6 | s) * 64 + d] = acc * (1.0f / 64.0f);
}

// ---------------------------------------------------------------------------
// B: per (bh,j): S=scale*qbar_j K^T; R=softmax_t; ent; kbar=R K; (vbar=R V)
// grid 4096, 256 thr
// ---------------------------------------------------------------------------
__global__ void __launch_bounds__(256)
bstep_kernel(const float* __restrict__ Kg, const float* __restrict__ Vg,
             int use_qmean, int do_vbar) {
    int bid = blockIdx.x, bh = bid >> 6, j = bid & 63;
    extern __shared__ char sm[];
    __nv_bfloat16* Ah = reinterpret_cast<__nv_bfloat16*>(sm + OFF_AH);  // qbar -> R
    __nv_bfloat16* Al = reinterpret_cast<__nv_bfloat16*>(sm + OFF_AL);
    __nv_bfloat16* Kh = reinterpret_cast<__nv_bfloat16*>(sm + OFF_BH);
    __nv_bfloat16* Kl = reinterpret_cast<__nv_bfloat16*>(sm + OFF_BL);
    __nv_bfloat16* Vh = reinterpret_cast<__nv_bfloat16*>(sm + OFF_VH);
    __nv_bfloat16* Vl = reinterpret_cast<__nv_bfloat16*>(sm + OFF_VL);
    float* C = reinterpret_cast<float*>(sm + OFF_C);
    int tid = threadIdx.x, wid = tid >> 5;

    const float* Kb = Kg + bh * 262144 + j * 4096;
    const float* qb = use_qmean ? (g_qmean + (bh << 12))
                                : (g_qbar + bh * 262144 + j * 4096);
    stageHL(Ah, Al, qb, 64, tid);
    stageHL(Kh, Kl, Kb, 64, tid);
    if (do_vbar) stageHL(Vh, Vl, Vg + bh * 262144 + j * 4096, 64, tid);
    __syncthreads();

    // S[s][t] = qbar(s,d) . K(t,d):  A row_major, B col_major over K(t,d)
    wgemm3<true, false>(Ah, Al, Kh, Kl, C, wid);
    __syncthreads();

    if (tid < 64) {
        int s = tid;
        float f[64];
        float mx = -1e30f;
#pragma unroll
        for (int c = 0; c < 64; ++c) {
            f[c] = C[s * LDC + c] * SCALE;
            mx = fmaxf(mx, f[c]);
        }
        float sum = 0.f;
#pragma unroll
        for (int c = 0; c < 64; ++c) { f[c] = __expf(f[c] - mx); sum += f[c]; }
        float inv = 1.0f / sum, lsum = __logf(sum), e = 0.f;
#pragma unroll
        for (int c = 0; c < 64; ++c) {
            float rv = f[c] * inv;
            e += rv * (__logf(fmaxf(f[c], 1e-37f)) - lsum);
            f[c] = rv;
        }
        g_ent[((bh << 6) + s) * 64 + j] = -e;
        stageRow(Ah, Al, f, s);              // R replaces qbar
    }
    __syncthreads();

    // kbar[s][d] = R(s,t) K(t,d): both row_major
    wgemm3<true, true>(Ah, Al, Kh, Kl, C, wid);
    __syncthreads();
    if (tid < 64) {
        float* o = g_kbar + bh * 262144 + tid * 4096 + (j << 6);
#pragma unroll
        for (int c = 0; c < 64; c += 4) {
            const float* p = C + tid * LDC + c;
            *reinterpret_cast<float4*>(o + c) = make_float4(p[0], p[1], p[2], p[3]);
        }
    }
    if (do_vbar) {
        __syncthreads();
        wgemm3<true, true>(Ah, Al, Vh, Vl, C, wid);
        __syncthreads();
        if (tid < 64) {
            float* o = g_vbar + bh * 262144 + tid * 4096 + (j << 6);
#pragma unroll
            for (int c = 0; c < 64; c += 4) {
                const float* p = C + tid * LDC + c;
                *reinterpret_cast<float4*>(o + c) = make_float4(p[0], p[1], p[2], p[3]);
            }
        }
    }
}

// ---------------------------------------------------------------------------
// C (fused): per (bh,s): SL = scale*Q kbar^T + ent; L = softmax_j
//   non-final: qbar[j][d] = (sum_i L[i][j] Q[i][d]) / (sum_i L[i][j])
//   final:     out[i][d] = sum_j L[i][j] vbar[j][d]
// grid 4096, 256 thr
// ---------------------------------------------------------------------------
__global__ void __launch_bounds__(256)
cstep_kernel(const float* __restrict__ Qg, float* __restrict__ out, int is_final) {
    int bid = blockIdx.x, bh = bid >> 6, s = bid & 63;
    extern __shared__ char sm[];
    __nv_bfloat16* Qh = reinterpret_cast<__nv_bfloat16*>(sm + OFF_AH);
    __nv_bfloat16* Ql = reinterpret_cast<__nv_bfloat16*>(sm + OFF_AL);
    __nv_bfloat16* Bh = reinterpret_cast<__nv_bfloat16*>(sm + OFF_BH);  // kbar -> L
    __nv_bfloat16* Bl = reinterpret_cast<__nv_bfloat16*>(sm + OFF_BL);
    __nv_bfloat16* Vh = reinterpret_cast<__nv_bfloat16*>(sm + OFF_VH);
    __nv_bfloat16* Vl = reinterpret_cast<__nv_bfloat16*>(sm + OFF_VL);
    float* C = reinterpret_cast<float*>(sm + OFF_C);
    float* sEnt = reinterpret_cast<float*>(sm + OFF_W);
    float* sW = sEnt + 64;
    int tid = threadIdx.x, wid = tid >> 5;

    const float* Qb = Qg + bh * 262144 + s * 64;       // rows i, stride 4096
    stageHL(Qh, Ql, Qb, 4096, tid);
    stageHL(Bh, Bl, g_kbar + bh * 262144 + s * 4096, 64, tid);
    if (is_final) stageHL(Vh, Vl, g_vbar + bh * 262144 + s * 4096, 64, tid);
    if (tid < 64) sEnt[tid] = g_ent[((bh << 6) + s) * 64 + tid];
    __syncthreads();

    // SL[i][j] = Q(i,d) . kbar(j,d): A row_major, B col_major
    wgemm3<true, false>(Qh, Ql, Bh, Bl, C, wid);
    __syncthreads();

    if (tid < 64) {
        int i = tid;
        float f[64];
        float mx = -1e30f;
#pragma unroll
        for (int c = 0; c < 64; ++c) {
            f[c] = C[i * LDC + c] * SCALE + sEnt[c];
            mx = fmaxf(mx, f[c]);
        }
        float sum = 0.f;
#pragma unroll
        for (int c = 0; c < 64; ++c) { f[c] = __expf(f[c] - mx); sum += f[c]; }
        float inv = 1.0f / sum;
#pragma unroll
        for (int c = 0; c < 64; ++c) f[c] *= inv;      // L row i
        stageRow(Bh, Bl, f, i);                         // L replaces kbar
        if (!is_final) {
#pragma unroll
            for (int c = 0; c < 64; ++c) C[i * LDC + c] = f[c];  // fp32 L for w
        }
    }
    __syncthreads();

    if (!is_final) {
        if (tid < 64) {
            float w = 0.f;
#pragma unroll 8
            for (int i = 0; i < 64; ++i) w += C[i * LDC + tid];
            sW[tid] = 1.0f / w;
        }
        __syncthreads();
        // qbar_num[j][d] = sum_i L(i,j) Q(i,d): A col_major over L(i,j), B row_major
        wgemm3<false, true>(Bh, Bl, Qh, Ql, C, wid);
        __syncthreads();
        if (tid < 64) {
            float iw = sW[tid];
            float* o = g_qbar + bh * 262144 + tid * 4096 + (s << 6);
#pragma unroll
            for (int c = 0; c < 64; c += 4) {
                const float* p = C + tid * LDC + c;
                *reinterpret_cast<float4*>(o + c) =
                    make_float4(p[0] * iw, p[1] * iw, p[2] * iw, p[3] * iw);
            }
        }
    } else {
        // out[i][d] = sum_j L(i,j) vbar(j,d): both row_major
        wgemm3<true, true>(Bh, Bl, Vh, Vl, C, wid);
        __syncthreads();
        if (tid < 64) {
            float* o = out + bh * 262144 + tid * 4096 + (s << 6);
#pragma unroll
            for (int c = 0; c < 64; c += 4) {
                const float* p = C + tid * LDC + c;
                *reinterpret_cast<float4*>(o + c) = make_float4(p[0], p[1], p[2], p[3]);
            }
        }
    }
}

// ---------------------------------------------------------------------------
extern "C" void kernel_launch(void* const* d_in, const int* in_sizes, int n_in,
                              void* d_out, int out_size) {
    const float* Q = (const float*)d_in[0];
    const float* K = (const float*)d_in[1];
    const float* V = (const float*)d_in[2];
    float* out = (float*)d_out;

    cudaFuncSetAttribute(bstep_kernel, cudaFuncAttributeMaxDynamicSharedMemorySize, SMEM_BIG);
    cudaFuncSetAttribute(cstep_kernel, cudaFuncAttributeMaxDynamicSharedMemorySize, SMEM_BIG);

    // step 0 (uniform L -> qbar == per-s mean of Q)
    qmean_kernel<<<1024, 256>>>(Q);
    bstep_kernel<<<4096, 256, SMEM_SMALL>>>(K, V, 1, 0);
    cstep_kernel<<<4096, 256, SMEM_SMALL>>>(Q, out, 0);
    // step 1
    bstep_kernel<<<4096, 256, SMEM_SMALL>>>(K, V, 0, 0);
    cstep_kernel<<<4096, 256, SMEM_SMALL>>>(Q, out, 0);
    // step 2
    bstep_kernel<<<4096, 256, SMEM_BIG>>>(K, V, 0, 1);   // + vbar
    cstep_kernel<<<4096, 256, SMEM_BIG>>>(Q, out, 1);    // final: out = L vbar
}